// round 1
// baseline (speedup 1.0000x reference)
#include <cuda_runtime.h>
#include <math.h>

#define EPSF 1e-6f
#define LOG_BIAS 1.0f
#define MAXS 4096
#define MAXW 64
#define HSTRIDE (MAXW + 2)   // per-head stride in segment table (seg index 0..MAXW)
#define MAXH 16
#define LUTN 4096

// Precomputed tables (device globals; zero-init, no allocation)
__device__ float  g_lr[MAXS];        // log_rel as function of d = |i-j|
__device__ float  g_invln[MAXS];     // 1 / log_norm as function of row i
__device__ float  g_bp[MAXW + 1];    // sorted breakpoints
__device__ float2 g_tab[MAXH * HSTRIDE];  // [h][seg] -> (slope, intercept)
__device__ unsigned char g_lut[LUTN];
__device__ int   g_nbp;
__device__ float g_ndlo;
__device__ float g_scale;

__global__ void fire_setup(const float* __restrict__ w1, const float* __restrict__ b1,
                           const float* __restrict__ w2, const float* __restrict__ b2,
                           const float* __restrict__ pc, const float* __restrict__ pLm,
                           const float* __restrict__ pInit, int S, int W, int H) {
    int t = threadIdx.x;
    float c   = *pc;
    float thr = fabsf((*pLm) * (*pInit));

    // log_rel[d] = log((d + eps)*c + 1 + eps)
    for (int d = t; d < S; d += blockDim.x)
        g_lr[d] = logf(((float)d + EPSF) * c + LOG_BIAS + EPSF);
    // inv log_norm[i] = 1 / log(|c * (max(i, thr) + eps)| + 1 + eps)
    for (int i = t; i < S; i += blockDim.x) {
        float pn = fmaxf((float)i, thr) + EPSF;
        g_invln[i] = 1.0f / logf(fabsf(c * pn) + LOG_BIAS + EPSF);
    }

    __shared__ float sbp[MAXW];
    __shared__ int   sidx[MAXW];
    __shared__ float sextra[MAXH];
    __shared__ int   snbp;
    __shared__ float sndlo, sscale;
    __syncthreads();

    if (t == 0) {
        // Collect breakpoints of relu(w1*nd + b1)
        int n = 0;
        for (int w = 0; w < W; w++) {
            float a = w1[w];
            if (a != 0.0f) { sbp[n] = -b1[w] / a; sidx[n] = w; n++; }
        }
        // insertion sort (n <= 64)
        for (int p = 1; p < n; p++) {
            float v = sbp[p]; int vi = sidx[p]; int q = p - 1;
            while (q >= 0 && sbp[q] > v) { sbp[q + 1] = sbp[q]; sidx[q + 1] = sidx[q]; q--; }
            sbp[q + 1] = v; sidx[q + 1] = vi;
        }
        snbp = n;
        g_nbp = n;
        // w1 == 0 weights: constant relu(b1) contribution
        for (int h = 0; h < H; h++) {
            float e = 0.0f;
            for (int w = 0; w < W; w++)
                if (w1[w] == 0.0f) e += w2[h * W + w] * fmaxf(b1[w], 0.0f);
            sextra[h] = e;
        }
        // nd range: lr and invln are monotone in d / i -> extremes at endpoints
        float l0 = g_lr[0], l1 = g_lr[S - 1];
        float i0 = g_invln[0], i1 = g_invln[S - 1];
        float p00 = l0 * i0, p01 = l0 * i1, p10 = l1 * i0, p11 = l1 * i1;
        float lo = fminf(fminf(p00, p01), fminf(p10, p11));
        float hi = fmaxf(fmaxf(p00, p01), fmaxf(p10, p11));
        float span = hi - lo;
        if (!(span > 0.0f)) span = 1.0f;
        sndlo  = lo;
        sscale = (float)LUTN / (span * (1.0f + 1e-5f));
        g_ndlo  = lo;
        g_scale = sscale;
    }
    __syncthreads();

    int n = snbp;
    if (t <= MAXW) g_bp[t] = (t < n) ? sbp[t] : __int_as_float(0x7f800000); // +inf pad

    // Per-segment slope/intercept tables.
    // seg(nd) = #(sorted bp <= nd). For sorted position p (weight w, a = w1[w]):
    //   active in segment s  <=>  (p < s) ? (a > 0) : (a < 0)
    // (boundary contributions are exactly zero -> exact piecewise representation)
    for (int s = t; s <= n; s += blockDim.x) {
        for (int h = 0; h < H; h++) {
            float slope = 0.0f;
            float inter = b2[h] + sextra[h];
            for (int p = 0; p < n; p++) {
                int w = sidx[p];
                float a = w1[w];
                bool act = (p < s) ? (a > 0.0f) : (a < 0.0f);
                if (act) {
                    float ww = w2[h * W + w];
                    slope += ww * a;
                    inter += ww * b1[w];
                }
            }
            g_tab[h * HSTRIDE + s] = make_float2(slope, inter);
        }
    }

    // Quantized LUT: segment count at each bin's left edge (refined exactly at use site)
    float lo = sndlo, sc = sscale;
    for (int k = t; k < LUTN; k += blockDim.x) {
        float bl = lo + (float)k / sc;
        int cnt = 0;
        for (int p = 0; p < n; p++) cnt += (sbp[p] <= bl) ? 1 : 0;
        g_lut[k] = (unsigned char)cnt;
    }
}

#define ROWS_PER_BLOCK 4

__global__ void __launch_bounds__(256)
fire_main(float* __restrict__ out, int S, int H) {
    __shared__ float         s_lr[MAXS];
    __shared__ unsigned char s_lut[LUTN];
    __shared__ float         s_bp[MAXW + 1];
    __shared__ float2        s_tab[MAXH * HSTRIDE];

    int t = threadIdx.x;
    for (int d = t; d < S; d += blockDim.x)        s_lr[d] = g_lr[d];
    for (int k = t; k < LUTN; k += blockDim.x)     s_lut[k] = g_lut[k];
    if (t <= MAXW)                                 s_bp[t] = g_bp[t];
    for (int k = t; k < MAXH * HSTRIDE; k += blockDim.x) s_tab[k] = g_tab[k];
    __syncthreads();

    const int   nbp   = g_nbp;
    const float ndlo  = g_ndlo;
    const float scale = g_scale;
    const size_t SS   = (size_t)S * (size_t)S;

    for (int r = 0; r < ROWS_PER_BLOCK; r++) {
        int i = blockIdx.x * ROWS_PER_BLOCK + r;
        if (i >= S) return;
        const float invln = g_invln[i];

        // vectorized path: 4 consecutive columns per thread per iteration
        for (int j0 = t * 4; j0 + 3 < S; j0 += blockDim.x * 4) {
            float nd[4];
            int   sg[4];
#pragma unroll
            for (int k = 0; k < 4; k++) {
                int j = j0 + k;
                int d = abs(i - j);
                float v = s_lr[d] * invln;
                nd[k] = v;
                int kq = (int)((v - ndlo) * scale);
                kq = max(0, min(LUTN - 1, kq));
                int s = (int)s_lut[kq];
                while (s > 0 && v < s_bp[s - 1]) s--;
                while (s < nbp && v >= s_bp[s]) s++;
                sg[k] = s;
            }
            float* op = out + (size_t)i * S + j0;
#pragma unroll 4
            for (int h = 0; h < H; h++) {
                const float2* th = &s_tab[h * HSTRIDE];
                float2 t0 = th[sg[0]], t1 = th[sg[1]], t2 = th[sg[2]], t3 = th[sg[3]];
                float4 o;
                o.x = fmaf(nd[0], t0.x, t0.y);
                o.y = fmaf(nd[1], t1.x, t1.y);
                o.z = fmaf(nd[2], t2.x, t2.y);
                o.w = fmaf(nd[3], t3.x, t3.y);
                *reinterpret_cast<float4*>(op + (size_t)h * SS) = o;
            }
        }

        // scalar tail (only if S % 4 != 0)
        int tail = S & ~3;
        for (int j = tail + t; j < S; j += blockDim.x) {
            int d = abs(i - j);
            float v = s_lr[d] * invln;
            int kq = (int)((v - ndlo) * scale);
            kq = max(0, min(LUTN - 1, kq));
            int s = (int)s_lut[kq];
            while (s > 0 && v < s_bp[s - 1]) s--;
            while (s < nbp && v >= s_bp[s]) s++;
            for (int h = 0; h < H; h++) {
                float2 ti = s_tab[h * HSTRIDE + s];
                out[(size_t)h * SS + (size_t)i * S + j] = fmaf(v, ti.x, ti.y);
            }
        }
    }
}

extern "C" void kernel_launch(void* const* d_in, const int* in_sizes, int n_in,
                              void* d_out, int out_size) {
    // metadata order: x, w1, b1, w2, b2, c, L_multiplier, init_L
    const float* w1 = (const float*)d_in[1];
    const float* b1 = (const float*)d_in[2];
    const float* w2 = (const float*)d_in[3];
    const float* b2 = (const float*)d_in[4];
    const float* c  = (const float*)d_in[5];
    const float* Lm = (const float*)d_in[6];
    const float* iL = (const float*)d_in[7];

    int W = in_sizes[2];          // width of hidden layer (b1 count)
    int H = in_sizes[4];          // number of heads (b2 count)
    long long SSll = (long long)out_size / (long long)H;
    int S = (int)(sqrt((double)SSll) + 0.5);

    fire_setup<<<1, 256>>>(w1, b1, w2, b2, c, Lm, iL, S, W, H);

    dim3 grid((S + ROWS_PER_BLOCK - 1) / ROWS_PER_BLOCK);
    fire_main<<<grid, 256>>>((float*)d_out, S, H);
}

// round 3
// speedup vs baseline: 1.4608x; 1.4608x over previous
#include <cuda_runtime.h>
#include <math.h>

#define EPSF 1e-6f
#define LOG_BIAS 1.0f
#define MAXS 4096
#define MAXW 64
#define HP 16                  // padded head stride in segment table
#define MAXH 16
#define LUTN 4096

// Precomputed tables (device globals; zero-init, no allocation)
__device__ float  g_lr[MAXS];          // log_rel as function of d = |i-j|
__device__ float  g_invln[MAXS];       // 1 / log_norm as function of row i
__device__ float  g_bp[MAXW + 1];      // sorted breakpoints (+inf padded)
__device__ int    g_sidx[MAXW];        // original weight index per sorted breakpoint
__device__ float  g_extra[MAXH];       // constant contribution from w1==0 weights
__device__ __align__(16) float2 g_tab[(MAXW + 1) * HP];  // [seg][head] -> (slope, intercept)
__device__ unsigned char g_lut[LUTN];
__device__ int   g_nbp;
__device__ float g_ndlo;
__device__ float g_scale;
__device__ float g_c, g_thr;

// ---------------- setup phase 1: tiny serial work (sort, scalars) --------------
__global__ void fire_setup1(const float* __restrict__ w1, const float* __restrict__ b1,
                            const float* __restrict__ w2, const float* __restrict__ b2,
                            const float* __restrict__ pc, const float* __restrict__ pLm,
                            const float* __restrict__ pInit, int S, int W, int H) {
    __shared__ float sbp[MAXW];
    __shared__ int   sidx[MAXW];
    __shared__ int   snbp;
    int t = threadIdx.x;
    float c   = *pc;
    float thr = fabsf((*pLm) * (*pInit));

    if (t == 0) {
        g_c = c; g_thr = thr;
        // Collect breakpoints of relu(w1*nd + b1)
        int n = 0;
        for (int w = 0; w < W; w++) {
            float a = w1[w];
            if (a != 0.0f) { sbp[n] = -b1[w] / a; sidx[n] = w; n++; }
        }
        // insertion sort (n <= 64)
        for (int p = 1; p < n; p++) {
            float v = sbp[p]; int vi = sidx[p]; int q = p - 1;
            while (q >= 0 && sbp[q] > v) { sbp[q + 1] = sbp[q]; sidx[q + 1] = sidx[q]; q--; }
            sbp[q + 1] = v; sidx[q + 1] = vi;
        }
        snbp = n;
        g_nbp = n;
        // nd range from monotone endpoints (LUT binning only; refine makes it exact)
        float l0 = logf(EPSF * c + LOG_BIAS + EPSF);
        float l1 = logf(((float)(S - 1) + EPSF) * c + LOG_BIAS + EPSF);
        float i0 = 1.0f / logf(fabsf(c * (fmaxf(0.0f, thr) + EPSF)) + LOG_BIAS + EPSF);
        float i1 = 1.0f / logf(fabsf(c * (fmaxf((float)(S - 1), thr) + EPSF)) + LOG_BIAS + EPSF);
        float p00 = l0 * i0, p01 = l0 * i1, p10 = l1 * i0, p11 = l1 * i1;
        float lo = fminf(fminf(p00, p01), fminf(p10, p11));
        float hi = fmaxf(fmaxf(p00, p01), fmaxf(p10, p11));
        float span = hi - lo;
        if (!(span > 0.0f)) span = 1.0f;
        g_ndlo  = lo;
        g_scale = (float)LUTN / (span * (1.0f + 1e-5f));
    }
    __syncthreads();
    int n = snbp;
    if (t <= MAXW) g_bp[t] = (t < n) ? sbp[t] : __int_as_float(0x7f800000);
    if (t < MAXW)  g_sidx[t] = (t < n) ? sidx[t] : 0;
    // w1 == 0 weights: constant relu(b1) contribution per head
    if (t < H) {
        float e = 0.0f;
        for (int w = 0; w < W; w++)
            if (w1[w] == 0.0f) e += w2[t * W + w] * fmaxf(b1[w], 0.0f);
        g_extra[t] = e;
    }
}

// ---------------- setup phase 2: parallel table fills --------------------------
__global__ void fire_setup2(const float* __restrict__ w1, const float* __restrict__ b1,
                            const float* __restrict__ w2, const float* __restrict__ b2,
                            int S, int W, int H) {
    __shared__ float sbp[MAXW + 1];
    int t = threadIdx.x;
    int gid = blockIdx.x * blockDim.x + t;
    int gtot = gridDim.x * blockDim.x;

    float c   = g_c;
    float thr = g_thr;
    int   n   = g_nbp;
    if (t <= MAXW) sbp[t] = g_bp[t];
    __syncthreads();

    // log tables
    for (int d = gid; d < S; d += gtot)
        g_lr[d] = logf(((float)d + EPSF) * c + LOG_BIAS + EPSF);
    for (int i = gid; i < S; i += gtot) {
        float pn = fmaxf((float)i, thr) + EPSF;
        g_invln[i] = 1.0f / logf(fabsf(c * pn) + LOG_BIAS + EPSF);
    }

    // Per-segment slope/intercept tables, layout [seg][head] (stride HP)
    // seg(nd) = #(sorted bp <= nd). Sorted position p (weight w, a = w1[w]):
    //   active in segment s  <=>  (p < s) ? (a > 0) : (a < 0)
    for (int e = gid; e < (n + 1) * H; e += gtot) {
        int s = e / H, h = e % H;
        float slope = 0.0f;
        float inter = b2[h] + g_extra[h];
        for (int p = 0; p < n; p++) {
            int w = g_sidx[p];
            float a = w1[w];
            bool act = (p < s) ? (a > 0.0f) : (a < 0.0f);
            if (act) {
                float ww = w2[h * W + w];
                slope += ww * a;
                inter += ww * b1[w];
            }
        }
        g_tab[s * HP + h] = make_float2(slope, inter);
    }

    // Quantized LUT via binary search (count of sbp <= bin left edge)
    float lo = g_ndlo, sc = g_scale;
    for (int k = gid; k < LUTN; k += gtot) {
        float bl = lo + (float)k / sc;
        int a = 0, b = n;
        while (a < b) {
            int mid = (a + b) >> 1;
            if (sbp[mid] <= bl) a = mid + 1; else b = mid;
        }
        g_lut[k] = (unsigned char)a;
    }
}

// ---------------- main kernel --------------------------------------------------
#define ROWS_PER_BLOCK 4

template <int H>
__global__ void __launch_bounds__(256)
fire_main(float* __restrict__ out, int S) {
    __shared__ float         s_lr[MAXS];
    __shared__ unsigned int  s_lut[LUTN / 4];
    __shared__ float         s_bp[MAXW + 1];
    __shared__ __align__(16) float2 s_tab[(MAXW + 1) * HP];

    int t = threadIdx.x;
    for (int d = t; d < S; d += blockDim.x)          s_lr[d] = g_lr[d];
    const unsigned int* glut = reinterpret_cast<const unsigned int*>(g_lut);
    for (int k = t; k < LUTN / 4; k += blockDim.x)   s_lut[k] = glut[k];
    if (t <= MAXW)                                   s_bp[t] = g_bp[t];
    for (int k = t; k < (MAXW + 1) * HP; k += blockDim.x) s_tab[k] = g_tab[k];
    __syncthreads();
    const unsigned char* s_lut8 = reinterpret_cast<const unsigned char*>(s_lut);

    const int   nbp   = g_nbp;
    const float ndlo  = g_ndlo;
    const float scale = g_scale;
    const size_t SS   = (size_t)S * (size_t)S;

    for (int r = 0; r < ROWS_PER_BLOCK; r++) {
        int i = blockIdx.x * ROWS_PER_BLOCK + r;
        if (i >= S) return;
        const float invln = g_invln[i];

        for (int j0 = t * 4; j0 + 3 < S; j0 += blockDim.x * 4) {
            float nd[4];
            int   sg[4];
#pragma unroll
            for (int k = 0; k < 4; k++) {
                int j = j0 + k;
                int d = abs(i - j);
                float v = s_lr[d] * invln;
                nd[k] = v;
                int kq = (int)((v - ndlo) * scale);
                kq = max(0, min(LUTN - 1, kq));
                int s = (int)s_lut8[kq];
                while (s > 0 && v < s_bp[s - 1]) s--;
                while (s < nbp && v >= s_bp[s]) s++;
                sg[k] = s;
            }
            float* op = out + (size_t)i * S + j0;
            int s0 = sg[0];
            if (s0 == sg[1] && s0 == sg[2] && s0 == sg[3]) {
                // uniform segment: 12 heads' (slope,intercept) as 6 LDS.128 broadcasts
                const float4* t4 = reinterpret_cast<const float4*>(s_tab + s0 * HP);
#pragma unroll
                for (int hh = 0; hh < H / 2; hh++) {
                    float4 p = t4[hh];     // head 2hh: (x,y); head 2hh+1: (z,w)
                    float4 o0, o1;
                    o0.x = fmaf(nd[0], p.x, p.y);
                    o0.y = fmaf(nd[1], p.x, p.y);
                    o0.z = fmaf(nd[2], p.x, p.y);
                    o0.w = fmaf(nd[3], p.x, p.y);
                    o1.x = fmaf(nd[0], p.z, p.w);
                    o1.y = fmaf(nd[1], p.z, p.w);
                    o1.z = fmaf(nd[2], p.z, p.w);
                    o1.w = fmaf(nd[3], p.z, p.w);
                    *reinterpret_cast<float4*>(op + (size_t)(2 * hh)     * SS) = o0;
                    *reinterpret_cast<float4*>(op + (size_t)(2 * hh + 1) * SS) = o1;
                }
                if (H & 1) {
                    float2 p = s_tab[s0 * HP + (H - 1)];
                    float4 o;
                    o.x = fmaf(nd[0], p.x, p.y);
                    o.y = fmaf(nd[1], p.x, p.y);
                    o.z = fmaf(nd[2], p.x, p.y);
                    o.w = fmaf(nd[3], p.x, p.y);
                    *reinterpret_cast<float4*>(op + (size_t)(H - 1) * SS) = o;
                }
            } else {
                // segment boundary straddles the 4 cols (rare): per-col gather
#pragma unroll 4
                for (int h = 0; h < H; h++) {
                    float2 t0 = s_tab[sg[0] * HP + h];
                    float2 t1 = s_tab[sg[1] * HP + h];
                    float2 t2 = s_tab[sg[2] * HP + h];
                    float2 t3 = s_tab[sg[3] * HP + h];
                    float4 o;
                    o.x = fmaf(nd[0], t0.x, t0.y);
                    o.y = fmaf(nd[1], t1.x, t1.y);
                    o.z = fmaf(nd[2], t2.x, t2.y);
                    o.w = fmaf(nd[3], t3.x, t3.y);
                    *reinterpret_cast<float4*>(op + (size_t)h * SS) = o;
                }
            }
        }

        // scalar tail (only if S % 4 != 0)
        int tail = S & ~3;
        for (int j = tail + t; j < S; j += blockDim.x) {
            int d = abs(i - j);
            float v = s_lr[d] * invln;
            int kq = (int)((v - ndlo) * scale);
            kq = max(0, min(LUTN - 1, kq));
            int s = (int)s_lut8[kq];
            while (s > 0 && v < s_bp[s - 1]) s--;
            while (s < nbp && v >= s_bp[s]) s++;
            for (int h = 0; h < H; h++) {
                float2 ti = s_tab[s * HP + h];
                out[(size_t)h * SS + (size_t)i * S + j] = fmaf(v, ti.x, ti.y);
            }
        }
    }
}

// generic-H fallback (same algorithm, runtime H)
__global__ void __launch_bounds__(256)
fire_main_gen(float* __restrict__ out, int S, int H) {
    __shared__ float         s_lr[MAXS];
    __shared__ unsigned int  s_lut[LUTN / 4];
    __shared__ float         s_bp[MAXW + 1];
    __shared__ __align__(16) float2 s_tab[(MAXW + 1) * HP];

    int t = threadIdx.x;
    for (int d = t; d < S; d += blockDim.x)          s_lr[d] = g_lr[d];
    const unsigned int* glut = reinterpret_cast<const unsigned int*>(g_lut);
    for (int k = t; k < LUTN / 4; k += blockDim.x)   s_lut[k] = glut[k];
    if (t <= MAXW)                                   s_bp[t] = g_bp[t];
    for (int k = t; k < (MAXW + 1) * HP; k += blockDim.x) s_tab[k] = g_tab[k];
    __syncthreads();
    const unsigned char* s_lut8 = reinterpret_cast<const unsigned char*>(s_lut);

    const int   nbp   = g_nbp;
    const float ndlo  = g_ndlo;
    const float scale = g_scale;
    const size_t SS   = (size_t)S * (size_t)S;

    for (int r = 0; r < ROWS_PER_BLOCK; r++) {
        int i = blockIdx.x * ROWS_PER_BLOCK + r;
        if (i >= S) return;
        const float invln = g_invln[i];
        for (int j = t; j < S; j += blockDim.x) {
            int d = abs(i - j);
            float v = s_lr[d] * invln;
            int kq = (int)((v - ndlo) * scale);
            kq = max(0, min(LUTN - 1, kq));
            int s = (int)s_lut8[kq];
            while (s > 0 && v < s_bp[s - 1]) s--;
            while (s < nbp && v >= s_bp[s]) s++;
            for (int h = 0; h < H; h++) {
                float2 ti = s_tab[s * HP + h];
                out[(size_t)h * SS + (size_t)i * S + j] = fmaf(v, ti.x, ti.y);
            }
        }
    }
}

extern "C" void kernel_launch(void* const* d_in, const int* in_sizes, int n_in,
                              void* d_out, int out_size) {
    // metadata order: x, w1, b1, w2, b2, c, L_multiplier, init_L
    const float* w1 = (const float*)d_in[1];
    const float* b1 = (const float*)d_in[2];
    const float* w2 = (const float*)d_in[3];
    const float* b2 = (const float*)d_in[4];
    const float* c  = (const float*)d_in[5];
    const float* Lm = (const float*)d_in[6];
    const float* iL = (const float*)d_in[7];

    int W = in_sizes[2];
    int H = in_sizes[4];
    long long SSll = (long long)out_size / (long long)H;
    int S = (int)(sqrt((double)SSll) + 0.5);

    fire_setup1<<<1, 128>>>(w1, b1, w2, b2, c, Lm, iL, S, W, H);
    fire_setup2<<<64, 256>>>(w1, b1, w2, b2, S, W, H);

    dim3 grid((S + ROWS_PER_BLOCK - 1) / ROWS_PER_BLOCK);
    if (H == 12)
        fire_main<12><<<grid, 256>>>((float*)d_out, S);
    else
        fire_main_gen<<<grid, 256>>>((float*)d_out, S, H);
}

// round 4
// speedup vs baseline: 1.5022x; 1.0284x over previous
#include <cuda_runtime.h>
#include <math.h>

#define EPSF 1e-6f
#define LOG_BIAS 1.0f
#define MAXS 4096
#define MAXW 64
#define HP 16                  // padded head stride in segment table
#define MAXH 16
#define LUTN 4096

// Precomputed tables (device globals; zero-init, no allocation)
__device__ float  g_lr[MAXS];          // log_rel as function of d = |i-j|
__device__ float  g_invln[MAXS];       // 1 / log_norm as function of row i
__device__ float  g_bp[MAXW + 1];      // sorted breakpoints (+inf padded)
__device__ int    g_sidx[MAXW];        // original weight index per sorted breakpoint
__device__ float  g_extra[MAXH];       // constant contribution from w1==0 weights
__device__ __align__(16) float2 g_tab[(MAXW + 1) * HP];  // [seg][head] -> (slope, intercept)
__device__ unsigned char g_lut[LUTN];
__device__ int   g_nbp;
__device__ float g_ndlo;
__device__ float g_scale;
__device__ float g_c, g_thr;

// ---------------- setup phase 1: parallel prefetch + tiny serial sort ----------
__global__ void fire_setup1(const float* __restrict__ w1, const float* __restrict__ b1,
                            const float* __restrict__ w2, const float* __restrict__ b2,
                            const float* __restrict__ pc, const float* __restrict__ pLm,
                            const float* __restrict__ pInit, int S, int W, int H) {
    __shared__ float sw1[MAXW], sb1[MAXW];
    __shared__ float sw2[MAXH * MAXW];
    __shared__ float sbp[MAXW];
    __shared__ int   sidx[MAXW];
    __shared__ int   snbp;
    __shared__ float s_c, s_thr;

    int t = threadIdx.x;
    // cooperative prefetch of all small params into smem (parallel LDG, one round trip)
    if (t < W) { sw1[t] = w1[t]; sb1[t] = b1[t]; }
    for (int k = t; k < H * W; k += blockDim.x) sw2[k] = w2[k];
    if (t == 0) {
        s_c   = *pc;
        s_thr = fabsf((*pLm) * (*pInit));
    }
    __syncthreads();

    float c   = s_c;
    float thr = s_thr;

    if (t == 0) {
        g_c = c; g_thr = thr;
        // Collect breakpoints of relu(w1*nd + b1) (smem only — no serial LDG chain)
        int n = 0;
        for (int w = 0; w < W; w++) {
            float a = sw1[w];
            if (a != 0.0f) { sbp[n] = -sb1[w] / a; sidx[n] = w; n++; }
        }
        // insertion sort (n <= 64)
        for (int p = 1; p < n; p++) {
            float v = sbp[p]; int vi = sidx[p]; int q = p - 1;
            while (q >= 0 && sbp[q] > v) { sbp[q + 1] = sbp[q]; sidx[q + 1] = sidx[q]; q--; }
            sbp[q + 1] = v; sidx[q + 1] = vi;
        }
        snbp = n;
        g_nbp = n;
        // nd range from monotone endpoints (LUT binning only; refine makes it exact)
        float l0 = logf(EPSF * c + LOG_BIAS + EPSF);
        float l1 = logf(((float)(S - 1) + EPSF) * c + LOG_BIAS + EPSF);
        float i0 = 1.0f / logf(fabsf(c * (fmaxf(0.0f, thr) + EPSF)) + LOG_BIAS + EPSF);
        float i1 = 1.0f / logf(fabsf(c * (fmaxf((float)(S - 1), thr) + EPSF)) + LOG_BIAS + EPSF);
        float p00 = l0 * i0, p01 = l0 * i1, p10 = l1 * i0, p11 = l1 * i1;
        float lo = fminf(fminf(p00, p01), fminf(p10, p11));
        float hi = fmaxf(fmaxf(p00, p01), fmaxf(p10, p11));
        float span = hi - lo;
        if (!(span > 0.0f)) span = 1.0f;
        g_ndlo  = lo;
        g_scale = (float)LUTN / (span * (1.0f + 1e-5f));
    }
    __syncthreads();
    int n = snbp;
    if (t <= MAXW) g_bp[t] = (t < n) ? sbp[t] : __int_as_float(0x7f800000);
    if (t < MAXW)  g_sidx[t] = (t < n) ? sidx[t] : 0;
    // w1 == 0 weights: constant relu(b1) contribution per head (smem reads)
    if (t < H) {
        float e = 0.0f;
        for (int w = 0; w < W; w++)
            if (sw1[w] == 0.0f) e += sw2[t * W + w] * fmaxf(sb1[w], 0.0f);
        g_extra[t] = e;
    }
}

// ---------------- setup phase 2: parallel table fills --------------------------
__global__ void fire_setup2(const float* __restrict__ w1, const float* __restrict__ b1,
                            const float* __restrict__ w2, const float* __restrict__ b2,
                            int S, int W, int H) {
    __shared__ float sbp[MAXW + 1];
    int t = threadIdx.x;
    int gid = blockIdx.x * blockDim.x + t;
    int gtot = gridDim.x * blockDim.x;

    float c   = g_c;
    float thr = g_thr;
    int   n   = g_nbp;
    if (t <= MAXW) sbp[t] = g_bp[t];
    __syncthreads();

    // log tables
    for (int d = gid; d < S; d += gtot)
        g_lr[d] = logf(((float)d + EPSF) * c + LOG_BIAS + EPSF);
    for (int i = gid; i < S; i += gtot) {
        float pn = fmaxf((float)i, thr) + EPSF;
        g_invln[i] = 1.0f / logf(fabsf(c * pn) + LOG_BIAS + EPSF);
    }

    // Per-segment slope/intercept tables, layout [seg][head] (stride HP)
    // seg(nd) = #(sorted bp <= nd). Sorted position p (weight w, a = w1[w]):
    //   active in segment s  <=>  (p < s) ? (a > 0) : (a < 0)
    for (int e = gid; e < (n + 1) * H; e += gtot) {
        int s = e / H, h = e % H;
        float slope = 0.0f;
        float inter = b2[h] + g_extra[h];
        for (int p = 0; p < n; p++) {
            int w = g_sidx[p];
            float a = w1[w];
            bool act = (p < s) ? (a > 0.0f) : (a < 0.0f);
            if (act) {
                float ww = w2[h * W + w];
                slope += ww * a;
                inter += ww * b1[w];
            }
        }
        g_tab[s * HP + h] = make_float2(slope, inter);
    }

    // Quantized LUT via binary search (count of sbp <= bin left edge)
    float lo = g_ndlo, sc = g_scale;
    for (int k = gid; k < LUTN; k += gtot) {
        float bl = lo + (float)k / sc;
        int a = 0, b = n;
        while (a < b) {
            int mid = (a + b) >> 1;
            if (sbp[mid] <= bl) a = mid + 1; else b = mid;
        }
        g_lut[k] = (unsigned char)a;
    }
}

// ---------------- main kernel --------------------------------------------------
#define ROWS_PER_BLOCK 4

template <int H>
__global__ void __launch_bounds__(256)
fire_main(float* __restrict__ out, int S) {
    __shared__ float         s_lr[MAXS];
    __shared__ unsigned int  s_lut[LUTN / 4];
    __shared__ float         s_bp[MAXW + 1];
    __shared__ __align__(16) float2 s_tab[(MAXW + 1) * HP];

    int t = threadIdx.x;
    for (int d = t; d < S; d += blockDim.x)          s_lr[d] = g_lr[d];
    const unsigned int* glut = reinterpret_cast<const unsigned int*>(g_lut);
    for (int k = t; k < LUTN / 4; k += blockDim.x)   s_lut[k] = glut[k];
    if (t <= MAXW)                                   s_bp[t] = g_bp[t];
    for (int k = t; k < (MAXW + 1) * HP; k += blockDim.x) s_tab[k] = g_tab[k];
    __syncthreads();
    const unsigned char* s_lut8 = reinterpret_cast<const unsigned char*>(s_lut);

    const int   nbp   = g_nbp;
    const float ndlo  = g_ndlo;
    const float scale = g_scale;
    const size_t SS   = (size_t)S * (size_t)S;

    for (int r = 0; r < ROWS_PER_BLOCK; r++) {
        int i = blockIdx.x * ROWS_PER_BLOCK + r;
        if (i >= S) return;
        const float invln = g_invln[i];

        for (int j0 = t * 4; j0 + 3 < S; j0 += blockDim.x * 4) {
            float nd[4];
            int   sg[4];
#pragma unroll
            for (int k = 0; k < 4; k++) {
                int j = j0 + k;
                int d = abs(i - j);
                float v = s_lr[d] * invln;
                nd[k] = v;
                int kq = (int)((v - ndlo) * scale);
                kq = max(0, min(LUTN - 1, kq));
                int s = (int)s_lut8[kq];
                while (s > 0 && v < s_bp[s - 1]) s--;
                while (s < nbp && v >= s_bp[s]) s++;
                sg[k] = s;
            }
            float* op = out + (size_t)i * S + j0;
            int s0 = sg[0];
            if (s0 == sg[1] && s0 == sg[2] && s0 == sg[3]) {
                // uniform segment: 12 heads' (slope,intercept) as 6 LDS.128 broadcasts
                const float4* t4 = reinterpret_cast<const float4*>(s_tab + s0 * HP);
#pragma unroll
                for (int hh = 0; hh < H / 2; hh++) {
                    float4 p = t4[hh];     // head 2hh: (x,y); head 2hh+1: (z,w)
                    float4 o0, o1;
                    o0.x = fmaf(nd[0], p.x, p.y);
                    o0.y = fmaf(nd[1], p.x, p.y);
                    o0.z = fmaf(nd[2], p.x, p.y);
                    o0.w = fmaf(nd[3], p.x, p.y);
                    o1.x = fmaf(nd[0], p.z, p.w);
                    o1.y = fmaf(nd[1], p.z, p.w);
                    o1.z = fmaf(nd[2], p.z, p.w);
                    o1.w = fmaf(nd[3], p.z, p.w);
                    *reinterpret_cast<float4*>(op + (size_t)(2 * hh)     * SS) = o0;
                    *reinterpret_cast<float4*>(op + (size_t)(2 * hh + 1) * SS) = o1;
                }
                if (H & 1) {
                    float2 p = s_tab[s0 * HP + (H - 1)];
                    float4 o;
                    o.x = fmaf(nd[0], p.x, p.y);
                    o.y = fmaf(nd[1], p.x, p.y);
                    o.z = fmaf(nd[2], p.x, p.y);
                    o.w = fmaf(nd[3], p.x, p.y);
                    *reinterpret_cast<float4*>(op + (size_t)(H - 1) * SS) = o;
                }
            } else {
                // segment boundary straddles the 4 cols (rare): per-col gather
#pragma unroll 4
                for (int h = 0; h < H; h++) {
                    float2 t0 = s_tab[sg[0] * HP + h];
                    float2 t1 = s_tab[sg[1] * HP + h];
                    float2 t2 = s_tab[sg[2] * HP + h];
                    float2 t3 = s_tab[sg[3] * HP + h];
                    float4 o;
                    o.x = fmaf(nd[0], t0.x, t0.y);
                    o.y = fmaf(nd[1], t1.x, t1.y);
                    o.z = fmaf(nd[2], t2.x, t2.y);
                    o.w = fmaf(nd[3], t3.x, t3.y);
                    *reinterpret_cast<float4*>(op + (size_t)h * SS) = o;
                }
            }
        }

        // scalar tail (only if S % 4 != 0)
        int tail = S & ~3;
        for (int j = tail + t; j < S; j += blockDim.x) {
            int d = abs(i - j);
            float v = s_lr[d] * invln;
            int kq = (int)((v - ndlo) * scale);
            kq = max(0, min(LUTN - 1, kq));
            int s = (int)s_lut8[kq];
            while (s > 0 && v < s_bp[s - 1]) s--;
            while (s < nbp && v >= s_bp[s]) s++;
            for (int h = 0; h < H; h++) {
                float2 ti = s_tab[s * HP + h];
                out[(size_t)h * SS + (size_t)i * S + j] = fmaf(v, ti.x, ti.y);
            }
        }
    }
}

// generic-H fallback (same algorithm, runtime H)
__global__ void __launch_bounds__(256)
fire_main_gen(float* __restrict__ out, int S, int H) {
    __shared__ float         s_lr[MAXS];
    __shared__ unsigned int  s_lut[LUTN / 4];
    __shared__ float         s_bp[MAXW + 1];
    __shared__ __align__(16) float2 s_tab[(MAXW + 1) * HP];

    int t = threadIdx.x;
    for (int d = t; d < S; d += blockDim.x)          s_lr[d] = g_lr[d];
    const unsigned int* glut = reinterpret_cast<const unsigned int*>(g_lut);
    for (int k = t; k < LUTN / 4; k += blockDim.x)   s_lut[k] = glut[k];
    if (t <= MAXW)                                   s_bp[t] = g_bp[t];
    for (int k = t; k < (MAXW + 1) * HP; k += blockDim.x) s_tab[k] = g_tab[k];
    __syncthreads();
    const unsigned char* s_lut8 = reinterpret_cast<const unsigned char*>(s_lut);

    const int   nbp   = g_nbp;
    const float ndlo  = g_ndlo;
    const float scale = g_scale;
    const size_t SS   = (size_t)S * (size_t)S;

    for (int r = 0; r < ROWS_PER_BLOCK; r++) {
        int i = blockIdx.x * ROWS_PER_BLOCK + r;
        if (i >= S) return;
        const float invln = g_invln[i];
        for (int j = t; j < S; j += blockDim.x) {
            int d = abs(i - j);
            float v = s_lr[d] * invln;
            int kq = (int)((v - ndlo) * scale);
            kq = max(0, min(LUTN - 1, kq));
            int s = (int)s_lut8[kq];
            while (s > 0 && v < s_bp[s - 1]) s--;
            while (s < nbp && v >= s_bp[s]) s++;
            for (int h = 0; h < H; h++) {
                float2 ti = s_tab[s * HP + h];
                out[(size_t)h * SS + (size_t)i * S + j] = fmaf(v, ti.x, ti.y);
            }
        }
    }
}

extern "C" void kernel_launch(void* const* d_in, const int* in_sizes, int n_in,
                              void* d_out, int out_size) {
    // metadata order: x, w1, b1, w2, b2, c, L_multiplier, init_L
    const float* w1 = (const float*)d_in[1];
    const float* b1 = (const float*)d_in[2];
    const float* w2 = (const float*)d_in[3];
    const float* b2 = (const float*)d_in[4];
    const float* c  = (const float*)d_in[5];
    const float* Lm = (const float*)d_in[6];
    const float* iL = (const float*)d_in[7];

    int W = in_sizes[2];
    int H = in_sizes[4];
    long long SSll = (long long)out_size / (long long)H;
    int S = (int)(sqrt((double)SSll) + 0.5);

    fire_setup1<<<1, 128>>>(w1, b1, w2, b2, c, Lm, iL, S, W, H);
    fire_setup2<<<64, 256>>>(w1, b1, w2, b2, S, W, H);

    dim3 grid((S + ROWS_PER_BLOCK - 1) / ROWS_PER_BLOCK);
    if (H == 12)
        fire_main<12><<<grid, 256>>>((float*)d_out, S);
    else
        fire_main_gen<<<grid, 256>>>((float*)d_out, S, H);
}

// round 5
// speedup vs baseline: 1.9567x; 1.3025x over previous
#include <cuda_runtime.h>
#include <math.h>

#define EPSF 1e-6f
#define LOG_BIAS 1.0f
#define MAXS 4096
#define MAXW 64
#define HP 16                  // padded head stride in segment table
#define MAXH 16
#define LUTN 4096

// Precomputed tables (device globals; zero-init, no allocation)
__device__ float  g_lr[MAXS];          // log_rel as function of d = |i-j|
__device__ float  g_invln[MAXS];       // 1 / log_norm as function of row i
__device__ float  g_bp[MAXW + 1];      // sorted breakpoints (+inf padded)
__device__ __align__(16) float2 g_tab[(MAXW + 1) * HP];  // [seg][head] -> (slope, intercept)
__device__ unsigned char g_lut[LUTN];
__device__ int   g_nbp;
__device__ float g_ndlo;
__device__ float g_scale;

// ---------------- unified setup: every block redundantly rank-sorts ------------
__global__ void __launch_bounds__(256)
fire_setup(const float* __restrict__ w1, const float* __restrict__ b1,
           const float* __restrict__ w2, const float* __restrict__ b2,
           const float* __restrict__ pc, const float* __restrict__ pLm,
           const float* __restrict__ pInit, int S, int W, int H) {
    __shared__ float sw1[MAXW], sb1[MAXW];
    __shared__ float s_raw_bp[MAXW];
    __shared__ float s_bp[MAXW + 1];    // sorted, +inf padded
    __shared__ int   s_sidx[MAXW];      // original weight index per sorted slot
    __shared__ float s_extra[MAXH];

    int t = threadIdx.x;
    int gid = blockIdx.x * blockDim.x + t;
    int gtot = gridDim.x * blockDim.x;
    const float INF = __int_as_float(0x7f800000);

    // parallel prefetch of small params (same-address loads broadcast via cache)
    if (t < MAXW) {
        sw1[t] = (t < W) ? w1[t] : 0.0f;
        sb1[t] = (t < W) ? b1[t] : 0.0f;
    }
    float c   = *pc;
    float thr = fabsf((*pLm) * (*pInit));
    __syncthreads();

    // raw breakpoints (+inf for invalid / padded entries)
    if (t < MAXW) {
        float a = sw1[t];
        s_raw_bp[t] = (t < W && a != 0.0f) ? (-sb1[t] / a) : INF;
    }
    int valid = (t < W) && (t < MAXW) && (sw1[t] != 0.0f);
    int n = __syncthreads_count(valid);   // number of real breakpoints (also syncs)

    // parallel rank sort: thread e counts elements strictly before it
    if (t < MAXW) {
        float mybp = s_raw_bp[t];
        int rank = 0;
#pragma unroll
        for (int m = 0; m < MAXW; m++) {
            float o = s_raw_bp[m];
            rank += (o < mybp || (o == mybp && m < t)) ? 1 : 0;
        }
        s_bp[rank] = mybp;          // invalid (inf) entries land at the tail
        s_sidx[rank] = t;
    }
    if (t == 0) s_bp[MAXW] = INF;
    __syncthreads();

    // nd range from monotone endpoints (LUT binning only; refine at use is exact)
    float l0 = logf(EPSF * c + LOG_BIAS + EPSF);
    float l1 = logf(((float)(S - 1) + EPSF) * c + LOG_BIAS + EPSF);
    float i0 = 1.0f / logf(fabsf(c * (fmaxf(0.0f, thr) + EPSF)) + LOG_BIAS + EPSF);
    float i1 = 1.0f / logf(fabsf(c * (fmaxf((float)(S - 1), thr) + EPSF)) + LOG_BIAS + EPSF);
    float p00 = l0 * i0, p01 = l0 * i1, p10 = l1 * i0, p11 = l1 * i1;
    float lo = fminf(fminf(p00, p01), fminf(p10, p11));
    float hi = fmaxf(fmaxf(p00, p01), fmaxf(p10, p11));
    float span = hi - lo;
    if (!(span > 0.0f)) span = 1.0f;
    float scale = (float)LUTN / (span * (1.0f + 1e-5f));

    // block 0 publishes scalars + sorted breakpoints for fire_main
    if (blockIdx.x == 0) {
        if (t == 0) { g_nbp = n; g_ndlo = lo; g_scale = scale; }
        if (t <= MAXW) g_bp[t] = s_bp[t];
    }

    // log tables (grid-strided)
    for (int d = gid; d < S; d += gtot)
        g_lr[d] = logf(((float)d + EPSF) * c + LOG_BIAS + EPSF);
    for (int i = gid; i < S; i += gtot) {
        float pn = fmaxf((float)i, thr) + EPSF;
        g_invln[i] = 1.0f / logf(fabsf(c * pn) + LOG_BIAS + EPSF);
    }

    // segment tables: only the first couple of blocks have work; they also need
    // the constant contribution of w1==0 weights
    if (blockIdx.x * blockDim.x < (n + 1) * H) {
        if (t < H) {
            float e = 0.0f;
            for (int w = 0; w < W; w++)
                if (sw1[w] == 0.0f) e += w2[t * W + w] * fmaxf(sb1[w], 0.0f);
            s_extra[t] = e;
        }
        __syncthreads();
        // [seg][head] layout (stride HP). seg(nd) = #(sorted bp <= nd).
        // Sorted position p (weight w, a = w1[w]) is active in segment s
        //   <=>  (p < s) ? (a > 0) : (a < 0)
        for (int e = gid; e < (n + 1) * H; e += gtot) {
            int s = e / H, h = e % H;
            float slope = 0.0f;
            float inter = b2[h] + s_extra[h];
            for (int p = 0; p < n; p++) {
                int w = s_sidx[p];
                float a = sw1[w];
                bool act = (p < s) ? (a > 0.0f) : (a < 0.0f);
                if (act) {
                    float ww = w2[h * W + w];
                    slope += ww * a;
                    inter += ww * sb1[w];
                }
            }
            g_tab[s * HP + h] = make_float2(slope, inter);
        }
    }

    // quantized LUT via binary search (count of sorted bp <= bin left edge)
    for (int k = gid; k < LUTN; k += gtot) {
        float bl = lo + (float)k / scale;
        int a = 0, b = n;
        while (a < b) {
            int mid = (a + b) >> 1;
            if (s_bp[mid] <= bl) a = mid + 1; else b = mid;
        }
        g_lut[k] = (unsigned char)a;
    }
}

// ---------------- main kernel --------------------------------------------------
#define ROWS_PER_BLOCK 4

template <int H>
__global__ void __launch_bounds__(256)
fire_main(float* __restrict__ out, int S) {
    __shared__ float         s_lr[MAXS];
    __shared__ unsigned int  s_lut[LUTN / 4];
    __shared__ float         s_bp[MAXW + 1];
    __shared__ __align__(16) float2 s_tab[(MAXW + 1) * HP];

    int t = threadIdx.x;
    for (int d = t; d < S; d += blockDim.x)          s_lr[d] = g_lr[d];
    const unsigned int* glut = reinterpret_cast<const unsigned int*>(g_lut);
    for (int k = t; k < LUTN / 4; k += blockDim.x)   s_lut[k] = glut[k];
    if (t <= MAXW)                                   s_bp[t] = g_bp[t];
    for (int k = t; k < (MAXW + 1) * HP; k += blockDim.x) s_tab[k] = g_tab[k];
    __syncthreads();
    const unsigned char* s_lut8 = reinterpret_cast<const unsigned char*>(s_lut);

    const int   nbp   = g_nbp;
    const float ndlo  = g_ndlo;
    const float scale = g_scale;
    const size_t SS   = (size_t)S * (size_t)S;

    for (int r = 0; r < ROWS_PER_BLOCK; r++) {
        int i = blockIdx.x * ROWS_PER_BLOCK + r;
        if (i >= S) return;
        const float invln = g_invln[i];

        for (int j0 = t * 4; j0 + 3 < S; j0 += blockDim.x * 4) {
            float nd[4];
            int   sg[4];
#pragma unroll
            for (int k = 0; k < 4; k++) {
                int j = j0 + k;
                int d = abs(i - j);
                float v = s_lr[d] * invln;
                nd[k] = v;
                int kq = (int)((v - ndlo) * scale);
                kq = max(0, min(LUTN - 1, kq));
                int s = (int)s_lut8[kq];
                while (s > 0 && v < s_bp[s - 1]) s--;
                while (s < nbp && v >= s_bp[s]) s++;
                sg[k] = s;
            }
            float* op = out + (size_t)i * S + j0;
            int s0 = sg[0];
            if (s0 == sg[1] && s0 == sg[2] && s0 == sg[3]) {
                // uniform segment: 12 heads' (slope,intercept) as 6 LDS.128 broadcasts
                const float4* t4 = reinterpret_cast<const float4*>(s_tab + s0 * HP);
#pragma unroll
                for (int hh = 0; hh < H / 2; hh++) {
                    float4 p = t4[hh];     // head 2hh: (x,y); head 2hh+1: (z,w)
                    float4 o0, o1;
                    o0.x = fmaf(nd[0], p.x, p.y);
                    o0.y = fmaf(nd[1], p.x, p.y);
                    o0.z = fmaf(nd[2], p.x, p.y);
                    o0.w = fmaf(nd[3], p.x, p.y);
                    o1.x = fmaf(nd[0], p.z, p.w);
                    o1.y = fmaf(nd[1], p.z, p.w);
                    o1.z = fmaf(nd[2], p.z, p.w);
                    o1.w = fmaf(nd[3], p.z, p.w);
                    *reinterpret_cast<float4*>(op + (size_t)(2 * hh)     * SS) = o0;
                    *reinterpret_cast<float4*>(op + (size_t)(2 * hh + 1) * SS) = o1;
                }
                if (H & 1) {
                    float2 p = s_tab[s0 * HP + (H - 1)];
                    float4 o;
                    o.x = fmaf(nd[0], p.x, p.y);
                    o.y = fmaf(nd[1], p.x, p.y);
                    o.z = fmaf(nd[2], p.x, p.y);
                    o.w = fmaf(nd[3], p.x, p.y);
                    *reinterpret_cast<float4*>(op + (size_t)(H - 1) * SS) = o;
                }
            } else {
                // segment boundary straddles the 4 cols (rare): per-col gather
#pragma unroll 4
                for (int h = 0; h < H; h++) {
                    float2 t0 = s_tab[sg[0] * HP + h];
                    float2 t1 = s_tab[sg[1] * HP + h];
                    float2 t2 = s_tab[sg[2] * HP + h];
                    float2 t3 = s_tab[sg[3] * HP + h];
                    float4 o;
                    o.x = fmaf(nd[0], t0.x, t0.y);
                    o.y = fmaf(nd[1], t1.x, t1.y);
                    o.z = fmaf(nd[2], t2.x, t2.y);
                    o.w = fmaf(nd[3], t3.x, t3.y);
                    *reinterpret_cast<float4*>(op + (size_t)h * SS) = o;
                }
            }
        }

        // scalar tail (only if S % 4 != 0)
        int tail = S & ~3;
        for (int j = tail + t; j < S; j += blockDim.x) {
            int d = abs(i - j);
            float v = s_lr[d] * invln;
            int kq = (int)((v - ndlo) * scale);
            kq = max(0, min(LUTN - 1, kq));
            int s = (int)s_lut8[kq];
            while (s > 0 && v < s_bp[s - 1]) s--;
            while (s < nbp && v >= s_bp[s]) s++;
            for (int h = 0; h < H; h++) {
                float2 ti = s_tab[s * HP + h];
                out[(size_t)h * SS + (size_t)i * S + j] = fmaf(v, ti.x, ti.y);
            }
        }
    }
}

// generic-H fallback (same algorithm, runtime H)
__global__ void __launch_bounds__(256)
fire_main_gen(float* __restrict__ out, int S, int H) {
    __shared__ float         s_lr[MAXS];
    __shared__ unsigned int  s_lut[LUTN / 4];
    __shared__ float         s_bp[MAXW + 1];
    __shared__ __align__(16) float2 s_tab[(MAXW + 1) * HP];

    int t = threadIdx.x;
    for (int d = t; d < S; d += blockDim.x)          s_lr[d] = g_lr[d];
    const unsigned int* glut = reinterpret_cast<const unsigned int*>(g_lut);
    for (int k = t; k < LUTN / 4; k += blockDim.x)   s_lut[k] = glut[k];
    if (t <= MAXW)                                   s_bp[t] = g_bp[t];
    for (int k = t; k < (MAXW + 1) * HP; k += blockDim.x) s_tab[k] = g_tab[k];
    __syncthreads();
    const unsigned char* s_lut8 = reinterpret_cast<const unsigned char*>(s_lut);

    const int   nbp   = g_nbp;
    const float ndlo  = g_ndlo;
    const float scale = g_scale;
    const size_t SS   = (size_t)S * (size_t)S;

    for (int r = 0; r < ROWS_PER_BLOCK; r++) {
        int i = blockIdx.x * ROWS_PER_BLOCK + r;
        if (i >= S) return;
        const float invln = g_invln[i];
        for (int j = t; j < S; j += blockDim.x) {
            int d = abs(i - j);
            float v = s_lr[d] * invln;
            int kq = (int)((v - ndlo) * scale);
            kq = max(0, min(LUTN - 1, kq));
            int s = (int)s_lut8[kq];
            while (s > 0 && v < s_bp[s - 1]) s--;
            while (s < nbp && v >= s_bp[s]) s++;
            for (int h = 0; h < H; h++) {
                float2 ti = s_tab[s * HP + h];
                out[(size_t)h * SS + (size_t)i * S + j] = fmaf(v, ti.x, ti.y);
            }
        }
    }
}

extern "C" void kernel_launch(void* const* d_in, const int* in_sizes, int n_in,
                              void* d_out, int out_size) {
    // metadata order: x, w1, b1, w2, b2, c, L_multiplier, init_L
    const float* w1 = (const float*)d_in[1];
    const float* b1 = (const float*)d_in[2];
    const float* w2 = (const float*)d_in[3];
    const float* b2 = (const float*)d_in[4];
    const float* c  = (const float*)d_in[5];
    const float* Lm = (const float*)d_in[6];
    const float* iL = (const float*)d_in[7];

    int W = in_sizes[2];
    int H = in_sizes[4];
    long long SSll = (long long)out_size / (long long)H;
    int S = (int)(sqrt((double)SSll) + 0.5);

    fire_setup<<<64, 256>>>(w1, b1, w2, b2, c, Lm, iL, S, W, H);

    dim3 grid((S + ROWS_PER_BLOCK - 1) / ROWS_PER_BLOCK);
    if (H == 12)
        fire_main<12><<<grid, 256>>>((float*)d_out, S);
    else
        fire_main_gen<<<grid, 256>>>((float*)d_out, S, H);
}